// round 10
// baseline (speedup 1.0000x reference)
#include <cuda_runtime.h>
#include <cstdint>

// VoxelHashTable R5: 2 queries/warp, lane = (half<<4)|(level<<3)|c.
// Phase 1: c = corner -> hash + h2v gather (one divergent LDG for all 32 combos).
// Weights for all 8 corners recomputed locally per lane (no w shuffle).
// Phase 2: c = channel-group-of-4 -> 8 iterations, each: 1 SHFL.IDX of v
// (per-lane source (lane&~7)|i serves all 4 (query,level) groups at once),
// 1 LDG.128 feature gather, 4 FFMA. One STG.128 store.

#define TMASK 0xFFFFF
#define P0 73856093
#define P1 19349669
#define P2 83492791

__global__ __launch_bounds__(256)
void voxel_hash_kernel3(const float* __restrict__ q,
                        const float* __restrict__ feats0,
                        const float* __restrict__ feats1,
                        const int*   __restrict__ h2v0,
                        const int*   __restrict__ h2v1,
                        float* __restrict__ out,
                        int M)
{
    const int warp  = (blockIdx.x * blockDim.x + threadIdx.x) >> 5;
    const int lane  = threadIdx.x & 31;
    const int half  = lane >> 4;         // query within warp
    const int qi    = warp * 2 + half;
    const int level = (lane >> 3) & 1;   // hash level
    const int c     = lane & 7;          // corner (phase 1) / channel-group (phase 2)

    const bool q_ok = qi < M;
    const int  qs   = q_ok ? qi : 0;

    // ---- Phase 1: per-lane fracs for (query, level); hash+gather for corner c ----
    const float res = level ? 0.24f : 0.12f;
    const float qx = q[qs*3 + 0];
    const float qy = q[qs*3 + 1];
    const float qz = q[qs*3 + 2];
    // IEEE round-to-nearest division (matches jnp q/res exactly)
    const float sx = __fdiv_rn(qx, res);
    const float sy = __fdiv_rn(qy, res);
    const float sz = __fdiv_rn(qz, res);
    const float bfx = floorf(sx), bfy = floorf(sy), bfz = floorf(sz);
    const float fx = sx - bfx, fy = sy - bfy, fz = sz - bfz;

    const int ox = (c >> 2) & 1, oy = (c >> 1) & 1, oz = c & 1;
    // int32 wrap-multiply == jax int32; &TMASK == mod 2^20
    const int hv = (((int)bfx + ox) * P0 + ((int)bfy + oy) * P1
                  + ((int)bfz + oz) * P2) & TMASK;

    const int* __restrict__ h2v = level ? h2v1 : h2v0;
    const int v = h2v[hv];               // 32 random 4B gathers in one LDG

    // ---- All 8 trilinear weights for this lane's (query, level), locally ----
    // product order matches jnp.prod: ((wx*wy)*wz)
    const float gx = 1.0f - fx, gy = 1.0f - fy, gz = 1.0f - fz;
    float pxy[4];
    pxy[0] = gx * gy;  pxy[1] = gx * fy;
    pxy[2] = fx * gy;  pxy[3] = fx * fy;
    float w8[8];
    #pragma unroll
    for (int k = 0; k < 8; k++)
        w8[k] = pxy[k >> 1] * ((k & 1) ? fz : gz);

    // ---- Phase 2: c = channel-group. Gather float4 per corner, accumulate ----
    const float* __restrict__ tab = level ? feats1 : feats0;
    const float* __restrict__ tabc = tab + c * 4;   // this lane's 4 channels
    const int src_base = lane & ~7;                  // same (half, level) group

    float4 acc = make_float4(0.0f, 0.0f, 0.0f, 0.0f);

    #pragma unroll
    for (int i = 0; i < 8; i++) {
        int vv = __shfl_sync(0xffffffffu, v, src_base + i);
        const float ww = (vv < 0) ? 0.0f : w8[i];    // invalid corner -> weight 0
        vv = (vv < 0) ? 0 : vv;
        const float4 f = *reinterpret_cast<const float4*>(tabc + (size_t)vv * 32);
        acc.x = fmaf(f.x, ww, acc.x);
        acc.y = fmaf(f.y, ww, acc.y);
        acc.z = fmaf(f.z, ww, acc.z);
        acc.w = fmaf(f.w, ww, acc.w);
    }

    if (q_ok) {
        float* o = out + (size_t)qi * 64 + level * 32 + c * 4;
        *reinterpret_cast<float4*>(o) = acc;
    }
}

extern "C" void kernel_launch(void* const* d_in, const int* in_sizes, int n_in,
                              void* d_out, int out_size)
{
    const float* q      = (const float*)d_in[0];
    const float* feats0 = (const float*)d_in[1];
    const float* feats1 = (const float*)d_in[2];
    const int*   h2v0   = (const int*)d_in[3];
    const int*   h2v1   = (const int*)d_in[4];
    float* out = (float*)d_out;

    const int M = in_sizes[0] / 3;                 // 500000
    const int threads = 256;                       // 8 warps = 16 queries/block
    const int qpb = (threads / 32) * 2;
    const int blocks = (M + qpb - 1) / qpb;

    voxel_hash_kernel3<<<blocks, threads>>>(q, feats0, feats1, h2v0, h2v1, out, M);
}

// round 17
// speedup vs baseline: 1.0079x; 1.0079x over previous
#include <cuda_runtime.h>
#include <cstdint>

// VoxelHashTable R6: 4 queries/warp = two pipelined query-pairs.
// Lane mapping per pair (as R5): lane = (half<<4)|(level<<3)|c.
//   Phase 1: c = corner -> hash + h2v gather (both pairs' gathers issued up front).
//   Weights for all 8 corners recomputed locally per lane (FMA pipe, hides gather).
//   Phase 2: c = channel-group-of-4 -> per corner: SHFL.IDX of v, LDG.128, 4 FFMA.
// Two independent chains per warp double memory-level parallelism (latency-bound fix).

#define TMASK 0xFFFFF
#define P0 73856093
#define P1 19349669
#define P2 83492791

__global__ __launch_bounds__(256)
void voxel_hash_kernel4(const float* __restrict__ q,
                        const float* __restrict__ feats0,
                        const float* __restrict__ feats1,
                        const int*   __restrict__ h2v0,
                        const int*   __restrict__ h2v1,
                        float* __restrict__ out,
                        int M)
{
    const int warp  = (blockIdx.x * blockDim.x + threadIdx.x) >> 5;
    const int lane  = threadIdx.x & 31;
    const int half  = lane >> 4;         // query within pair
    const int level = (lane >> 3) & 1;   // hash level
    const int c     = lane & 7;          // corner (phase 1) / channel-group (phase 2)

    const int qi0 = warp * 4 + half;         // pair 0
    const int qi1 = warp * 4 + 2 + half;     // pair 1
    const bool ok0 = qi0 < M;
    const bool ok1 = qi1 < M;
    const int qs0 = ok0 ? qi0 : 0;
    const int qs1 = ok1 ? qi1 : 0;

    const float res = level ? 0.24f : 0.12f;
    const int ox = (c >> 2) & 1, oy = (c >> 1) & 1, oz = c & 1;
    const int* __restrict__ h2v = level ? h2v1 : h2v0;

    // ---- Phase 1 for BOTH pairs: hash + issue both h2v gathers early ----
    const float q0x = q[qs0*3+0], q0y = q[qs0*3+1], q0z = q[qs0*3+2];
    const float q1x = q[qs1*3+0], q1y = q[qs1*3+1], q1z = q[qs1*3+2];

    // IEEE round-to-nearest division (matches jnp q/res exactly)
    const float s0x = __fdiv_rn(q0x, res), s0y = __fdiv_rn(q0y, res), s0z = __fdiv_rn(q0z, res);
    const float s1x = __fdiv_rn(q1x, res), s1y = __fdiv_rn(q1y, res), s1z = __fdiv_rn(q1z, res);

    const float b0x = floorf(s0x), b0y = floorf(s0y), b0z = floorf(s0z);
    const float b1x = floorf(s1x), b1y = floorf(s1y), b1z = floorf(s1z);

    // int32 wrap-multiply == jax int32; &TMASK == mod 2^20
    const int hv0 = (((int)b0x + ox) * P0 + ((int)b0y + oy) * P1 + ((int)b0z + oz) * P2) & TMASK;
    const int hv1 = (((int)b1x + ox) * P0 + ((int)b1y + oy) * P1 + ((int)b1z + oz) * P2) & TMASK;

    const int v0 = h2v[hv0];     // two independent divergent gathers in flight
    const int v1 = h2v[hv1];

    // ---- Weights for both pairs (FMA pipe work while gathers are in flight) ----
    const float f0x = s0x - b0x, f0y = s0y - b0y, f0z = s0z - b0z;
    const float f1x = s1x - b1x, f1y = s1y - b1y, f1z = s1z - b1z;
    // product order matches jnp.prod: ((wx*wy)*wz)
    const float g0x = 1.0f - f0x, g0y = 1.0f - f0y, g0z = 1.0f - f0z;
    const float g1x = 1.0f - f1x, g1y = 1.0f - f1y, g1z = 1.0f - f1z;

    float w8_0[8], w8_1[8];
    {
        float p0[4], p1[4];
        p0[0] = g0x*g0y; p0[1] = g0x*f0y; p0[2] = f0x*g0y; p0[3] = f0x*f0y;
        p1[0] = g1x*g1y; p1[1] = g1x*f1y; p1[2] = f1x*g1y; p1[3] = f1x*f1y;
        #pragma unroll
        for (int k = 0; k < 8; k++) {
            w8_0[k] = p0[k >> 1] * ((k & 1) ? f0z : g0z);
            w8_1[k] = p1[k >> 1] * ((k & 1) ? f1z : g1z);
        }
    }

    // ---- Phase 2: interleave both pairs' corner loops (16 independent LDG.128) ----
    const float* __restrict__ tab = level ? feats1 : feats0;
    const float* __restrict__ tabc = tab + c * 4;   // this lane's 4 channels
    const int src_base = lane & ~7;                 // same (half, level) group

    float4 acc0 = make_float4(0.f, 0.f, 0.f, 0.f);
    float4 acc1 = make_float4(0.f, 0.f, 0.f, 0.f);

    #pragma unroll
    for (int i = 0; i < 8; i++) {
        int vv0 = __shfl_sync(0xffffffffu, v0, src_base + i);
        int vv1 = __shfl_sync(0xffffffffu, v1, src_base + i);
        const float ww0 = (vv0 < 0) ? 0.0f : w8_0[i];
        const float ww1 = (vv1 < 0) ? 0.0f : w8_1[i];
        vv0 = (vv0 < 0) ? 0 : vv0;
        vv1 = (vv1 < 0) ? 0 : vv1;
        const float4 f0 = *reinterpret_cast<const float4*>(tabc + (size_t)vv0 * 32);
        const float4 f1 = *reinterpret_cast<const float4*>(tabc + (size_t)vv1 * 32);
        acc0.x = fmaf(f0.x, ww0, acc0.x);
        acc0.y = fmaf(f0.y, ww0, acc0.y);
        acc0.z = fmaf(f0.z, ww0, acc0.z);
        acc0.w = fmaf(f0.w, ww0, acc0.w);
        acc1.x = fmaf(f1.x, ww1, acc1.x);
        acc1.y = fmaf(f1.y, ww1, acc1.y);
        acc1.z = fmaf(f1.z, ww1, acc1.z);
        acc1.w = fmaf(f1.w, ww1, acc1.w);
    }

    const int sub_off = level * 32 + c * 4;
    if (ok0) *reinterpret_cast<float4*>(out + (size_t)qi0 * 64 + sub_off) = acc0;
    if (ok1) *reinterpret_cast<float4*>(out + (size_t)qi1 * 64 + sub_off) = acc1;
}

extern "C" void kernel_launch(void* const* d_in, const int* in_sizes, int n_in,
                              void* d_out, int out_size)
{
    const float* q      = (const float*)d_in[0];
    const float* feats0 = (const float*)d_in[1];
    const float* feats1 = (const float*)d_in[2];
    const int*   h2v0   = (const int*)d_in[3];
    const int*   h2v1   = (const int*)d_in[4];
    float* out = (float*)d_out;

    const int M = in_sizes[0] / 3;                 // 500000
    const int threads = 256;                       // 8 warps = 32 queries/block
    const int qpb = (threads / 32) * 4;
    const int blocks = (M + qpb - 1) / qpb;

    voxel_hash_kernel4<<<blocks, threads>>>(q, feats0, feats1, h2v0, h2v1, out, M);
}